// round 15
// baseline (speedup 1.0000x reference)
#include <cuda_runtime.h>
#include <cuda_fp16.h>
#include <stdint.h>

#define N_NODES_MAX 100000
#define N_EDGES_MAX 1250000
#define D_FEAT 64
#define SCAN_B 1024
#define CH_EPT 2   // int4 chunks per thread in hist/fill (= 8 edges)

// ---- static scratch (no cudaMalloc allowed) ----
__device__ __half g_xh[(size_t)N_NODES_MAX * D_FEAT];    // x in fp16
__device__ __half g_th[(size_t)N_NODES_MAX * D_FEAT];    // relu(conv1) in fp16
__device__ int    g_deg[N_NODES_MAX];
__device__ int    g_rowptr[N_NODES_MAX + 4];
__device__ int    g_rank[N_EDGES_MAX];
__device__ int    g_src_sorted[N_EDGES_MAX];
__device__ int    g_blocksums[128];
__device__ int    g_idx_is64;   // 1 = int64 indices, 0 = int32

// ---- fused prologue: block 0 = dtype probe; blocks [1,1+zb) = zero deg;
//      blocks [1+zb, ...) = fp32->fp16 convert ----
__global__ void prologue_kernel(const unsigned int* __restrict__ w,
                                const float* __restrict__ x,
                                __half* __restrict__ xh,
                                int* __restrict__ deg,
                                int n_nodes, int n_floats, int zb) {
    int b = blockIdx.x;
    if (b == 0) {
        int nz = 0;
        #pragma unroll
        for (int k = 0; k < 4; ++k) {
            int i = threadIdx.x * 4 + k;
            if (w[2 * i + 1] != 0u) nz = 1;
        }
        int any = __syncthreads_or(nz);
        if (threadIdx.x == 0) g_idx_is64 = any ? 0 : 1;
    } else if (b <= zb) {
        int i = (b - 1) * blockDim.x + threadIdx.x;
        if (i < n_nodes) deg[i] = 0;
    } else {
        int i = (b - 1 - zb) * blockDim.x + threadIdx.x;
        int base = i * 8;
        if (base + 7 < n_floats) {
            float4 a = *reinterpret_cast<const float4*>(x + base);
            float4 c = *reinterpret_cast<const float4*>(x + base + 4);
            __half2 h[4];
            h[0] = __floats2half2_rn(a.x, a.y);
            h[1] = __floats2half2_rn(a.z, a.w);
            h[2] = __floats2half2_rn(c.x, c.y);
            h[3] = __floats2half2_rn(c.z, c.w);
            *reinterpret_cast<uint4*>(xh + base) = *reinterpret_cast<uint4*>(h);
        } else if (base < n_floats) {
            for (int k = base; k < n_floats; ++k) xh[k] = __float2half_rn(x[k]);
        }
    }
}

// ---- histogram of dst; atomic return value = rank within dst segment ----
__global__ void hist_kernel(const void* __restrict__ ei, int* __restrict__ deg,
                            int* __restrict__ rank, int n_edges, int n_ct) {
    int is64 = g_idx_is64;
    int t = blockIdx.x * blockDim.x + threadIdx.x;
    if (t >= n_ct) return;
    if (!is64) {
        const int* dst = ((const int*)ei) + n_edges;
        int n_vec = n_edges >> 2;

        int c[CH_EPT]; bool v[CH_EPT]; int4 d[CH_EPT];
        #pragma unroll
        for (int k = 0; k < CH_EPT; ++k) {
            c[k] = t + k * n_ct;
            v[k] = (c[k] < n_vec);
            if (v[k]) d[k] = __ldg(((const int4*)dst) + c[k]);
        }
        int4 r[CH_EPT];
        #pragma unroll
        for (int k = 0; k < CH_EPT; ++k) {
            if (v[k]) {
                r[k].x = atomicAdd(&deg[d[k].x], 1);
                r[k].y = atomicAdd(&deg[d[k].y], 1);
                r[k].z = atomicAdd(&deg[d[k].z], 1);
                r[k].w = atomicAdd(&deg[d[k].w], 1);
            }
        }
        #pragma unroll
        for (int k = 0; k < CH_EPT; ++k)
            if (v[k]) *reinterpret_cast<int4*>(rank + c[k] * 4) = r[k];

        if (t == 0) {
            for (int e = n_vec * 4; e < n_edges; ++e)
                rank[e] = atomicAdd(&deg[__ldg(dst + e)], 1);
        }
    } else {
        const long long* dst = ((const long long*)ei) + n_edges;
        for (int k = 0; k < CH_EPT * 4; ++k) {
            long long e = (long long)t + (long long)k * n_ct;
            if (e < n_edges) rank[e] = atomicAdd(&deg[(int)__ldg(dst + e)], 1);
        }
        if (t == 0) {
            for (long long e = (long long)n_ct * 4 * CH_EPT; e < n_edges; ++e)
                rank[e] = atomicAdd(&deg[(int)__ldg(dst + e)], 1);
        }
    }
}

// ---- 3-kernel exclusive scan, 4 elements per thread (int4) ----
__global__ void scan1_kernel(const int* __restrict__ deg, int* __restrict__ rowptr,
                             int* __restrict__ blocksums, int n) {
    __shared__ int warp_sums[32];
    int t = threadIdx.x;
    int lane = t & 31, wid = t >> 5;
    int i0 = (blockIdx.x * SCAN_B + t) * 4;

    int4 v = make_int4(0, 0, 0, 0);
    if (i0 + 3 < n) {
        v = *reinterpret_cast<const int4*>(deg + i0);
    } else {
        if (i0 < n)     v.x = deg[i0];
        if (i0 + 1 < n) v.y = deg[i0 + 1];
        if (i0 + 2 < n) v.z = deg[i0 + 2];
        if (i0 + 3 < n) v.w = deg[i0 + 3];
    }
    int l1 = v.x + v.y;
    int l2 = l1 + v.z;
    int tot = l2 + v.w;

    int incl = tot;
    #pragma unroll
    for (int off = 1; off < 32; off <<= 1) {
        int u = __shfl_up_sync(0xffffffffu, incl, off);
        if (lane >= off) incl += u;
    }
    if (lane == 31) warp_sums[wid] = incl;
    __syncthreads();
    if (wid == 0) {
        int ws = warp_sums[lane];
        int wincl = ws;
        #pragma unroll
        for (int off = 1; off < 32; off <<= 1) {
            int u = __shfl_up_sync(0xffffffffu, wincl, off);
            if (lane >= off) wincl += u;
        }
        warp_sums[lane] = wincl - ws;   // exclusive warp offsets
        if (lane == 31) blocksums[blockIdx.x] = wincl;
    }
    __syncthreads();
    int base = incl - tot + warp_sums[wid];   // exclusive within block

    if (i0 + 3 < n) {
        *reinterpret_cast<int4*>(rowptr + i0) =
            make_int4(base, base + v.x, base + l1, base + l2);
    } else {
        if (i0 < n)     rowptr[i0]     = base;
        if (i0 + 1 < n) rowptr[i0 + 1] = base + v.x;
        if (i0 + 2 < n) rowptr[i0 + 2] = base + l1;
        if (i0 + 3 < n) rowptr[i0 + 3] = base + l2;
    }
}

__global__ void scan2_kernel(int* __restrict__ blocksums, int nb) {
    __shared__ int warp_sums[4];
    int t = threadIdx.x;
    int lane = t & 31, wid = t >> 5;
    int v = (t < nb) ? blocksums[t] : 0;
    int incl = v;
    #pragma unroll
    for (int off = 1; off < 32; off <<= 1) {
        int u = __shfl_up_sync(0xffffffffu, incl, off);
        if (lane >= off) incl += u;
    }
    if (lane == 31) warp_sums[wid] = incl;
    __syncthreads();
    int woff = 0;
    for (int k = 0; k < wid; ++k) woff += warp_sums[k];
    if (t < nb) blocksums[t] = incl - v + woff;   // exclusive
}

__global__ void scan3_kernel(int* __restrict__ rowptr, const int* __restrict__ blocksums,
                             int n, int n_edges) {
    int t = threadIdx.x;
    int i0 = (blockIdx.x * SCAN_B + t) * 4;
    int off = blocksums[blockIdx.x];
    if (i0 + 3 < n) {
        int4 r = *reinterpret_cast<int4*>(rowptr + i0);
        r.x += off; r.y += off; r.z += off; r.w += off;
        *reinterpret_cast<int4*>(rowptr + i0) = r;
    } else {
        if (i0 < n)     rowptr[i0]     += off;
        if (i0 + 1 < n) rowptr[i0 + 1] += off;
        if (i0 + 2 < n) rowptr[i0 + 2] += off;
        if (i0 + 3 < n) rowptr[i0 + 3] += off;
    }
    if (blockIdx.x == 0 && t == 0) rowptr[n] = n_edges;
}

// ---- fill dst-sorted src list (no atomics: rank precomputed) ----
__global__ void fill_kernel(const void* __restrict__ ei, const int* __restrict__ rowptr,
                            const int* __restrict__ rank, int* __restrict__ src_sorted,
                            int n_edges, int n_ct) {
    int is64 = g_idx_is64;
    int t = blockIdx.x * blockDim.x + threadIdx.x;
    if (t >= n_ct) return;
    if (!is64) {
        const int* srcp = (const int*)ei;
        const int* dstp = srcp + n_edges;
        int n_vec = n_edges >> 2;

        int c[CH_EPT]; bool v[CH_EPT];
        int4 s[CH_EPT], d[CH_EPT], r[CH_EPT];
        #pragma unroll
        for (int k = 0; k < CH_EPT; ++k) {
            c[k] = t + k * n_ct;
            v[k] = (c[k] < n_vec);
            if (v[k]) {
                s[k] = __ldg(((const int4*)srcp) + c[k]);
                d[k] = __ldg(((const int4*)dstp) + c[k]);
                r[k] = __ldg(((const int4*)rank) + c[k]);
            }
        }
        int4 p[CH_EPT];
        #pragma unroll
        for (int k = 0; k < CH_EPT; ++k) {
            if (v[k]) {
                p[k].x = __ldg(rowptr + d[k].x);
                p[k].y = __ldg(rowptr + d[k].y);
                p[k].z = __ldg(rowptr + d[k].z);
                p[k].w = __ldg(rowptr + d[k].w);
            }
        }
        #pragma unroll
        for (int k = 0; k < CH_EPT; ++k) {
            if (v[k]) {
                src_sorted[p[k].x + r[k].x] = s[k].x;
                src_sorted[p[k].y + r[k].y] = s[k].y;
                src_sorted[p[k].z + r[k].z] = s[k].z;
                src_sorted[p[k].w + r[k].w] = s[k].w;
            }
        }
        if (t == 0) {
            for (int e = n_vec * 4; e < n_edges; ++e)
                src_sorted[__ldg(rowptr + __ldg(dstp + e)) + __ldg(rank + e)] = __ldg(srcp + e);
        }
    } else {
        const long long* srcp = (const long long*)ei;
        for (int k = 0; k < CH_EPT * 4; ++k) {
            long long e = (long long)t + (long long)k * n_ct;
            if (e < n_edges) {
                int s = (int)__ldg(srcp + e);
                int dd = (int)__ldg(srcp + n_edges + e);
                src_sorted[__ldg(rowptr + dd) + __ldg(rank + e)] = s;
            }
        }
        if (t == 0) {
            for (long long e = (long long)n_ct * 4 * CH_EPT; e < n_edges; ++e) {
                int s = (int)__ldg(srcp + e);
                int dd = (int)__ldg(srcp + n_edges + e);
                src_sorted[__ldg(rowptr + dd) + __ldg(rank + e)] = s;
            }
        }
    }
}

// ---- aggregate pass 1: tmp_h[node] = half(relu(sum in_h[src])) ----
// 8 threads per node; each thread owns 8 feature halves (16B uint4 load).
__global__ void agg1_kernel(const __half* __restrict__ in,
                            const int* __restrict__ rowptr,
                            const int* __restrict__ src_sorted,
                            __half* __restrict__ out, int n_nodes) {
    int node = blockIdx.x * (blockDim.x >> 3) + (threadIdx.x >> 3);
    int lane = threadIdx.x & 7;
    if (node >= n_nodes) return;
    int beg = __ldg(rowptr + node);
    int end = __ldg(rowptr + node + 1);

    float acc[8];
    #pragma unroll
    for (int k = 0; k < 8; ++k) acc[k] = 0.f;

    int j = beg;
    for (; j + 1 < end; j += 2) {
        int s0 = __ldg(src_sorted + j);
        int s1 = __ldg(src_sorted + j + 1);
        uint4 a = __ldg((const uint4*)(in + (size_t)s0 * D_FEAT) + lane);
        uint4 b = __ldg((const uint4*)(in + (size_t)s1 * D_FEAT) + lane);
        const __half2* ha = (const __half2*)&a;
        const __half2* hb = (const __half2*)&b;
        #pragma unroll
        for (int k = 0; k < 4; ++k) {
            float2 fa = __half22float2(ha[k]);
            float2 fb = __half22float2(hb[k]);
            acc[2 * k]     += fa.x + fb.x;
            acc[2 * k + 1] += fa.y + fb.y;
        }
    }
    if (j < end) {
        int s = __ldg(src_sorted + j);
        uint4 a = __ldg((const uint4*)(in + (size_t)s * D_FEAT) + lane);
        const __half2* ha = (const __half2*)&a;
        #pragma unroll
        for (int k = 0; k < 4; ++k) {
            float2 fa = __half22float2(ha[k]);
            acc[2 * k]     += fa.x;
            acc[2 * k + 1] += fa.y;
        }
    }

    __half2 r[4];
    #pragma unroll
    for (int k = 0; k < 4; ++k)
        r[k] = __floats2half2_rn(fmaxf(acc[2 * k], 0.f), fmaxf(acc[2 * k + 1], 0.f));
    *reinterpret_cast<uint4*>(out + (size_t)node * D_FEAT + lane * 8) =
        *reinterpret_cast<uint4*>(r);
}

// ---- aggregate pass 2: out_f32[node] = sum tmp_h[src] ----
__global__ void agg2_kernel(const __half* __restrict__ in,
                            const int* __restrict__ rowptr,
                            const int* __restrict__ src_sorted,
                            float* __restrict__ out, int n_nodes) {
    int node = blockIdx.x * (blockDim.x >> 3) + (threadIdx.x >> 3);
    int lane = threadIdx.x & 7;
    if (node >= n_nodes) return;
    int beg = __ldg(rowptr + node);
    int end = __ldg(rowptr + node + 1);

    float acc[8];
    #pragma unroll
    for (int k = 0; k < 8; ++k) acc[k] = 0.f;

    int j = beg;
    for (; j + 1 < end; j += 2) {
        int s0 = __ldg(src_sorted + j);
        int s1 = __ldg(src_sorted + j + 1);
        uint4 a = __ldg((const uint4*)(in + (size_t)s0 * D_FEAT) + lane);
        uint4 b = __ldg((const uint4*)(in + (size_t)s1 * D_FEAT) + lane);
        const __half2* ha = (const __half2*)&a;
        const __half2* hb = (const __half2*)&b;
        #pragma unroll
        for (int k = 0; k < 4; ++k) {
            float2 fa = __half22float2(ha[k]);
            float2 fb = __half22float2(hb[k]);
            acc[2 * k]     += fa.x + fb.x;
            acc[2 * k + 1] += fa.y + fb.y;
        }
    }
    if (j < end) {
        int s = __ldg(src_sorted + j);
        uint4 a = __ldg((const uint4*)(in + (size_t)s * D_FEAT) + lane);
        const __half2* ha = (const __half2*)&a;
        #pragma unroll
        for (int k = 0; k < 4; ++k) {
            float2 fa = __half22float2(ha[k]);
            acc[2 * k]     += fa.x;
            acc[2 * k + 1] += fa.y;
        }
    }

    float* op = out + (size_t)node * D_FEAT + lane * 8;
    *reinterpret_cast<float4*>(op)     = make_float4(acc[0], acc[1], acc[2], acc[3]);
    *reinterpret_cast<float4*>(op + 4) = make_float4(acc[4], acc[5], acc[6], acc[7]);
}

extern "C" void kernel_launch(void* const* d_in, const int* in_sizes, int n_in,
                              void* d_out, int out_size) {
    const float* x = (const float*)d_in[0];   // [N_NODES, 64] f32
    const void* ei = d_in[1];                 // [2, N_EDGES] i64 or i32

    int n_edges = in_sizes[1] / 2;
    if (n_edges > N_EDGES_MAX) n_edges = N_EDGES_MAX;
    int n_nodes = in_sizes[0] / D_FEAT;
    if (n_nodes > N_NODES_MAX) n_nodes = N_NODES_MAX;
    int n_node_floats = in_sizes[0];

    float* out = (float*)d_out;

    __half *xh, *th; int *deg, *rowptr, *rank, *src_sorted, *blocksums;
    cudaGetSymbolAddress((void**)&xh, g_xh);
    cudaGetSymbolAddress((void**)&th, g_th);
    cudaGetSymbolAddress((void**)&deg, g_deg);
    cudaGetSymbolAddress((void**)&rowptr, g_rowptr);
    cudaGetSymbolAddress((void**)&rank, g_rank);
    cudaGetSymbolAddress((void**)&src_sorted, g_src_sorted);
    cudaGetSymbolAddress((void**)&blocksums, g_blocksums);

    // 1. fused prologue: dtype probe + deg zero + fp16 convert
    int zb = (n_nodes + 255) / 256;
    int cb = ((n_node_floats + 7) / 8 + 255) / 256;
    prologue_kernel<<<1 + zb + cb, 256>>>((const unsigned int*)ei, x, xh, deg,
                                          n_nodes, n_node_floats, zb);

    // 2. CSR build: histogram(+rank) -> scan (4 elem/thread) -> fill
    int n_vec = n_edges >> 2;
    int n_ct = (n_vec + CH_EPT - 1) / CH_EPT;
    if (n_ct < 1) n_ct = 1;
    hist_kernel<<<(n_ct + 255) / 256, 256>>>(ei, deg, rank, n_edges, n_ct);

    int nb4 = (n_nodes + SCAN_B * 4 - 1) / (SCAN_B * 4);   // <= 25
    scan1_kernel<<<nb4, SCAN_B>>>(deg, rowptr, blocksums, n_nodes);
    scan2_kernel<<<1, 128>>>(blocksums, nb4);
    scan3_kernel<<<nb4, SCAN_B>>>(rowptr, blocksums, n_nodes, n_edges);

    fill_kernel<<<(n_ct + 255) / 256, 256>>>(ei, rowptr, rank, src_sorted, n_edges, n_ct);

    // 3. two aggregation passes over fp16 features, fp32 accumulate
    int threads = 256;
    int nodes_per_block = threads / 8;
    int blocks = (n_nodes + nodes_per_block - 1) / nodes_per_block;

    agg1_kernel<<<blocks, threads>>>(xh, rowptr, src_sorted, th, n_nodes);
    agg2_kernel<<<blocks, threads>>>(th, rowptr, src_sorted, out, n_nodes);
}

// round 16
// speedup vs baseline: 1.3330x; 1.3330x over previous
#include <cuda_runtime.h>
#include <cuda_fp16.h>
#include <stdint.h>

#define N_NODES_MAX 100000
#define N_EDGES_MAX 1250000
#define D_FEAT 64
#define SCAN_B 1024
#define CH_EPT 4    // int4 chunks per thread in hist (= 16 edges)
#define FILL_EPT 2  // int4 chunks per thread in fill (= 8 edges)

// ---- static scratch (no cudaMalloc allowed) ----
__device__ __half g_xh[(size_t)N_NODES_MAX * D_FEAT];    // x in fp16
__device__ __half g_th[(size_t)N_NODES_MAX * D_FEAT];    // relu(conv1) in fp16
__device__ int    g_deg[N_NODES_MAX];
__device__ int    g_rowptr[N_NODES_MAX + 4];
__device__ int    g_rank[N_EDGES_MAX];
__device__ int    g_src_sorted[N_EDGES_MAX];
__device__ int    g_blocksums[128];
__device__ int    g_idx_is64;   // 1 = int64 indices, 0 = int32

// ---- block 0: index dtype probe; other blocks: zero deg ----
__global__ void detect_zero_kernel(const unsigned int* __restrict__ w,
                                   int* __restrict__ deg, int n_nodes) {
    if (blockIdx.x == 0) {
        int nz = 0;
        #pragma unroll
        for (int k = 0; k < 4; ++k) {
            int i = threadIdx.x * 4 + k;
            if (w[2 * i + 1] != 0u) nz = 1;
        }
        int any = __syncthreads_or(nz);
        if (threadIdx.x == 0) g_idx_is64 = any ? 0 : 1;
    } else {
        int i = (blockIdx.x - 1) * blockDim.x + threadIdx.x;
        if (i < n_nodes) deg[i] = 0;
    }
}

// ---- convert fp32 x -> fp16 (8 floats per thread) ----
__global__ void convert_kernel(const float* __restrict__ x, __half* __restrict__ xh,
                               int n_floats) {
    int i = blockIdx.x * blockDim.x + threadIdx.x;
    int base = i * 8;
    if (base + 7 < n_floats) {
        float4 a = *reinterpret_cast<const float4*>(x + base);
        float4 b = *reinterpret_cast<const float4*>(x + base + 4);
        __half2 h[4];
        h[0] = __floats2half2_rn(a.x, a.y);
        h[1] = __floats2half2_rn(a.z, a.w);
        h[2] = __floats2half2_rn(b.x, b.y);
        h[3] = __floats2half2_rn(b.z, b.w);
        *reinterpret_cast<uint4*>(xh + base) = *reinterpret_cast<uint4*>(h);
    } else {
        for (int k = base; k < n_floats; ++k) xh[k] = __float2half_rn(x[k]);
    }
}

// ---- histogram of dst; atomic return value = rank within dst segment ----
__global__ void hist_kernel(const void* __restrict__ ei, int* __restrict__ deg,
                            int* __restrict__ rank, int n_edges, int n_ct) {
    int is64 = g_idx_is64;
    int t = blockIdx.x * blockDim.x + threadIdx.x;
    if (t >= n_ct) return;
    if (!is64) {
        const int* dst = ((const int*)ei) + n_edges;
        int n_vec = n_edges >> 2;

        int c[CH_EPT]; bool v[CH_EPT]; int4 d[CH_EPT];
        #pragma unroll
        for (int k = 0; k < CH_EPT; ++k) {
            c[k] = t + k * n_ct;
            v[k] = (c[k] < n_vec);
            if (v[k]) d[k] = __ldg(((const int4*)dst) + c[k]);
        }
        int4 r[CH_EPT];
        #pragma unroll
        for (int k = 0; k < CH_EPT; ++k) {
            if (v[k]) {
                r[k].x = atomicAdd(&deg[d[k].x], 1);
                r[k].y = atomicAdd(&deg[d[k].y], 1);
                r[k].z = atomicAdd(&deg[d[k].z], 1);
                r[k].w = atomicAdd(&deg[d[k].w], 1);
            }
        }
        #pragma unroll
        for (int k = 0; k < CH_EPT; ++k)
            if (v[k]) *reinterpret_cast<int4*>(rank + c[k] * 4) = r[k];

        if (t == 0) {
            for (int e = n_vec * 4; e < n_edges; ++e)
                rank[e] = atomicAdd(&deg[__ldg(dst + e)], 1);
        }
    } else {
        const long long* dst = ((const long long*)ei) + n_edges;
        for (int k = 0; k < CH_EPT * 4; ++k) {
            long long e = (long long)t + (long long)k * n_ct;
            if (e < n_edges) rank[e] = atomicAdd(&deg[(int)__ldg(dst + e)], 1);
        }
        if (t == 0) {
            for (long long e = (long long)n_ct * 4 * CH_EPT; e < n_edges; ++e)
                rank[e] = atomicAdd(&deg[(int)__ldg(dst + e)], 1);
        }
    }
}

// ---- exclusive scan part 1: per-block scan + block sums (1 elem/thread) ----
__global__ void scan1_kernel(const int* __restrict__ deg, int* __restrict__ rowptr,
                             int* __restrict__ blocksums, int n) {
    __shared__ int warp_sums[32];
    int t = threadIdx.x;
    int lane = t & 31, wid = t >> 5;
    int i = blockIdx.x * SCAN_B + t;
    int v = (i < n) ? deg[i] : 0;
    int incl = v;
    #pragma unroll
    for (int off = 1; off < 32; off <<= 1) {
        int u = __shfl_up_sync(0xffffffffu, incl, off);
        if (lane >= off) incl += u;
    }
    if (lane == 31) warp_sums[wid] = incl;
    __syncthreads();
    if (wid == 0) {
        int ws = warp_sums[lane];
        int wincl = ws;
        #pragma unroll
        for (int off = 1; off < 32; off <<= 1) {
            int u = __shfl_up_sync(0xffffffffu, wincl, off);
            if (lane >= off) wincl += u;
        }
        warp_sums[lane] = wincl - ws;   // exclusive warp offsets
        if (lane == 31) blocksums[blockIdx.x] = wincl;
    }
    __syncthreads();
    if (i < n) rowptr[i] = incl - v + warp_sums[wid];
}

// ---- scan part 2 (merged scan2+scan3): each block directly reduces
//      blocksums[0..bid) (<=98 ints, warp-parallel) and adds the offset ----
__global__ void scan23_kernel(int* __restrict__ rowptr, const int* __restrict__ blocksums,
                              int n, int n_edges) {
    __shared__ int s_off;
    int t = threadIdx.x;
    int bid = blockIdx.x;
    if (t < 32) {
        int a = 0;
        for (int p = t; p < bid; p += 32) a += __ldg(blocksums + p);
        #pragma unroll
        for (int off = 16; off > 0; off >>= 1)
            a += __shfl_down_sync(0xffffffffu, a, off);
        if (t == 0) s_off = a;
    }
    __syncthreads();
    int i = bid * SCAN_B + t;
    if (i < n) rowptr[i] += s_off;
    if (i == 0) rowptr[n] = n_edges;
}

// ---- fill dst-sorted src list (no atomics: rank precomputed), EPT=8 ----
// launch_bounds caps regs (~42) so occupancy isn't the binding constraint
// (R13 profile: regs=72 -> occ 23.5%, issue 4.3%).
__global__ void __launch_bounds__(256, 6)
fill_kernel(const void* __restrict__ ei, const int* __restrict__ rowptr,
            const int* __restrict__ rank, int* __restrict__ src_sorted,
            int n_edges, int n_ct) {
    int is64 = g_idx_is64;
    int t = blockIdx.x * blockDim.x + threadIdx.x;
    if (t >= n_ct) return;
    if (!is64) {
        const int* srcp = (const int*)ei;
        const int* dstp = srcp + n_edges;
        int n_vec = n_edges >> 2;

        int c[FILL_EPT]; bool v[FILL_EPT];
        int4 s[FILL_EPT], d[FILL_EPT], r[FILL_EPT];
        #pragma unroll
        for (int k = 0; k < FILL_EPT; ++k) {
            c[k] = t + k * n_ct;
            v[k] = (c[k] < n_vec);
            if (v[k]) {
                s[k] = __ldg(((const int4*)srcp) + c[k]);
                d[k] = __ldg(((const int4*)dstp) + c[k]);
                r[k] = __ldg(((const int4*)rank) + c[k]);
            }
        }
        int4 p[FILL_EPT];
        #pragma unroll
        for (int k = 0; k < FILL_EPT; ++k) {
            if (v[k]) {
                p[k].x = __ldg(rowptr + d[k].x);
                p[k].y = __ldg(rowptr + d[k].y);
                p[k].z = __ldg(rowptr + d[k].z);
                p[k].w = __ldg(rowptr + d[k].w);
            }
        }
        #pragma unroll
        for (int k = 0; k < FILL_EPT; ++k) {
            if (v[k]) {
                src_sorted[p[k].x + r[k].x] = s[k].x;
                src_sorted[p[k].y + r[k].y] = s[k].y;
                src_sorted[p[k].z + r[k].z] = s[k].z;
                src_sorted[p[k].w + r[k].w] = s[k].w;
            }
        }
        if (t == 0) {
            for (int e = n_vec * 4; e < n_edges; ++e)
                src_sorted[__ldg(rowptr + __ldg(dstp + e)) + __ldg(rank + e)] = __ldg(srcp + e);
        }
    } else {
        const long long* srcp = (const long long*)ei;
        for (int k = 0; k < FILL_EPT * 4; ++k) {
            long long e = (long long)t + (long long)k * n_ct;
            if (e < n_edges) {
                int s = (int)__ldg(srcp + e);
                int dd = (int)__ldg(srcp + n_edges + e);
                src_sorted[__ldg(rowptr + dd) + __ldg(rank + e)] = s;
            }
        }
        if (t == 0) {
            for (long long e = (long long)n_ct * 4 * FILL_EPT; e < n_edges; ++e) {
                int s = (int)__ldg(srcp + e);
                int dd = (int)__ldg(srcp + n_edges + e);
                src_sorted[__ldg(rowptr + dd) + __ldg(rank + e)] = s;
            }
        }
    }
}

// ---- aggregate pass 1: tmp_h[node] = half(relu(sum in_h[src])) ----
// 8 threads per node; each thread owns 8 feature halves (16B uint4 load).
__global__ void agg1_kernel(const __half* __restrict__ in,
                            const int* __restrict__ rowptr,
                            const int* __restrict__ src_sorted,
                            __half* __restrict__ out, int n_nodes) {
    int node = blockIdx.x * (blockDim.x >> 3) + (threadIdx.x >> 3);
    int lane = threadIdx.x & 7;
    if (node >= n_nodes) return;
    int beg = __ldg(rowptr + node);
    int end = __ldg(rowptr + node + 1);

    float acc[8];
    #pragma unroll
    for (int k = 0; k < 8; ++k) acc[k] = 0.f;

    int j = beg;
    for (; j + 1 < end; j += 2) {
        int s0 = __ldg(src_sorted + j);
        int s1 = __ldg(src_sorted + j + 1);
        uint4 a = __ldg((const uint4*)(in + (size_t)s0 * D_FEAT) + lane);
        uint4 b = __ldg((const uint4*)(in + (size_t)s1 * D_FEAT) + lane);
        const __half2* ha = (const __half2*)&a;
        const __half2* hb = (const __half2*)&b;
        #pragma unroll
        for (int k = 0; k < 4; ++k) {
            float2 fa = __half22float2(ha[k]);
            float2 fb = __half22float2(hb[k]);
            acc[2 * k]     += fa.x + fb.x;
            acc[2 * k + 1] += fa.y + fb.y;
        }
    }
    if (j < end) {
        int s = __ldg(src_sorted + j);
        uint4 a = __ldg((const uint4*)(in + (size_t)s * D_FEAT) + lane);
        const __half2* ha = (const __half2*)&a;
        #pragma unroll
        for (int k = 0; k < 4; ++k) {
            float2 fa = __half22float2(ha[k]);
            acc[2 * k]     += fa.x;
            acc[2 * k + 1] += fa.y;
        }
    }

    __half2 r[4];
    #pragma unroll
    for (int k = 0; k < 4; ++k)
        r[k] = __floats2half2_rn(fmaxf(acc[2 * k], 0.f), fmaxf(acc[2 * k + 1], 0.f));
    *reinterpret_cast<uint4*>(out + (size_t)node * D_FEAT + lane * 8) =
        *reinterpret_cast<uint4*>(r);
}

// ---- aggregate pass 2: out_f32[node] = sum tmp_h[src] ----
__global__ void agg2_kernel(const __half* __restrict__ in,
                            const int* __restrict__ rowptr,
                            const int* __restrict__ src_sorted,
                            float* __restrict__ out, int n_nodes) {
    int node = blockIdx.x * (blockDim.x >> 3) + (threadIdx.x >> 3);
    int lane = threadIdx.x & 7;
    if (node >= n_nodes) return;
    int beg = __ldg(rowptr + node);
    int end = __ldg(rowptr + node + 1);

    float acc[8];
    #pragma unroll
    for (int k = 0; k < 8; ++k) acc[k] = 0.f;

    int j = beg;
    for (; j + 1 < end; j += 2) {
        int s0 = __ldg(src_sorted + j);
        int s1 = __ldg(src_sorted + j + 1);
        uint4 a = __ldg((const uint4*)(in + (size_t)s0 * D_FEAT) + lane);
        uint4 b = __ldg((const uint4*)(in + (size_t)s1 * D_FEAT) + lane);
        const __half2* ha = (const __half2*)&a;
        const __half2* hb = (const __half2*)&b;
        #pragma unroll
        for (int k = 0; k < 4; ++k) {
            float2 fa = __half22float2(ha[k]);
            float2 fb = __half22float2(hb[k]);
            acc[2 * k]     += fa.x + fb.x;
            acc[2 * k + 1] += fa.y + fb.y;
        }
    }
    if (j < end) {
        int s = __ldg(src_sorted + j);
        uint4 a = __ldg((const uint4*)(in + (size_t)s * D_FEAT) + lane);
        const __half2* ha = (const __half2*)&a;
        #pragma unroll
        for (int k = 0; k < 4; ++k) {
            float2 fa = __half22float2(ha[k]);
            acc[2 * k]     += fa.x;
            acc[2 * k + 1] += fa.y;
        }
    }

    float* op = out + (size_t)node * D_FEAT + lane * 8;
    *reinterpret_cast<float4*>(op)     = make_float4(acc[0], acc[1], acc[2], acc[3]);
    *reinterpret_cast<float4*>(op + 4) = make_float4(acc[4], acc[5], acc[6], acc[7]);
}

extern "C" void kernel_launch(void* const* d_in, const int* in_sizes, int n_in,
                              void* d_out, int out_size) {
    const float* x = (const float*)d_in[0];   // [N_NODES, 64] f32
    const void* ei = d_in[1];                 // [2, N_EDGES] i64 or i32

    int n_edges = in_sizes[1] / 2;
    if (n_edges > N_EDGES_MAX) n_edges = N_EDGES_MAX;
    int n_nodes = in_sizes[0] / D_FEAT;
    if (n_nodes > N_NODES_MAX) n_nodes = N_NODES_MAX;
    int n_node_floats = in_sizes[0];

    float* out = (float*)d_out;

    __half *xh, *th; int *deg, *rowptr, *rank, *src_sorted, *blocksums;
    cudaGetSymbolAddress((void**)&xh, g_xh);
    cudaGetSymbolAddress((void**)&th, g_th);
    cudaGetSymbolAddress((void**)&deg, g_deg);
    cudaGetSymbolAddress((void**)&rowptr, g_rowptr);
    cudaGetSymbolAddress((void**)&rank, g_rank);
    cudaGetSymbolAddress((void**)&src_sorted, g_src_sorted);
    cudaGetSymbolAddress((void**)&blocksums, g_blocksums);

    // 1. dtype probe + zero deg (one kernel) + fp16 convert
    {
        int zb = (n_nodes + 255) / 256;
        detect_zero_kernel<<<1 + zb, 256>>>((const unsigned int*)ei, deg, n_nodes);
    }
    {
        int n8 = (n_node_floats + 7) / 8;
        convert_kernel<<<(n8 + 255) / 256, 256>>>(x, xh, n_node_floats);
    }

    // 2. CSR build: histogram(+rank, EPT=16) -> scan (2 kernels) -> fill (EPT=8)
    int n_vec = n_edges >> 2;
    int n_ct_h = (n_vec + CH_EPT - 1) / CH_EPT;
    if (n_ct_h < 1) n_ct_h = 1;
    hist_kernel<<<(n_ct_h + 255) / 256, 256>>>(ei, deg, rank, n_edges, n_ct_h);

    int nb = (n_nodes + SCAN_B - 1) / SCAN_B;   // <= 98
    scan1_kernel<<<nb, SCAN_B>>>(deg, rowptr, blocksums, n_nodes);
    scan23_kernel<<<nb, SCAN_B>>>(rowptr, blocksums, n_nodes, n_edges);

    int n_ct_f = (n_vec + FILL_EPT - 1) / FILL_EPT;
    if (n_ct_f < 1) n_ct_f = 1;
    fill_kernel<<<(n_ct_f + 255) / 256, 256>>>(ei, rowptr, rank, src_sorted, n_edges, n_ct_f);

    // 3. two aggregation passes over fp16 features, fp32 accumulate
    int threads = 256;
    int nodes_per_block = threads / 8;
    int blocks = (n_nodes + nodes_per_block - 1) / nodes_per_block;

    agg1_kernel<<<blocks, threads>>>(xh, rowptr, src_sorted, th, n_nodes);
    agg2_kernel<<<blocks, threads>>>(th, rowptr, src_sorted, out, n_nodes);
}